// round 16
// baseline (speedup 1.0000x reference)
#include <cuda_runtime.h>
#include <cuda_fp16.h>
#include <cstdint>

// ---------------- Problem dims ----------------
static constexpr int T   = 20;
static constexpr int B   = 1024;
static constexpr int IN  = 2048;
static constexpr int OUT = 2048;
static constexpr int M   = T * B;          // 20480
static constexpr int K   = IN;             // 2048
static constexpr int N   = OUT;            // 2048

// GEMM tiling: A-tile 160 rows (= 20 t x 8 b, t-major) x BN=128, BK=64, 2 stages,
// 256 threads, 2 CTAs/SM. Warps: 2(m: 80 rows = 5 frags) x 4(n: 32 cols).
static constexpr int BROWS = 160;
static constexpr int BGRP  = 8;            // b values per CTA
static constexpr int BN    = 128;
static constexpr int BK    = 64;           // 64 halfs = 128B row
static constexpr int NCHUNK = K / BK;      // 32

static constexpr int A_TILE_B = BROWS * 128;       // 20480
static constexpr int W_TILE_B = 128 * 128;         // 16384
static constexpr int STAGE_B  = A_TILE_B + 2 * W_TILE_B;   // 53248
static constexpr int SMEM_B   = 2 * STAGE_B;               // 106496 (x2 CTA = 212992)

static constexpr int SSTRIDE = 132;        // scan smem stride (floats), 160*132*4=84480

// ---------------- scratch (no cudaMalloc allowed) ----------------
__device__ __half g_xh [(size_t)M * K];    // 84 MB  x in fp16 (exact: x is 0/1)
__device__ __half g_whi[(size_t)N * K];    // 8 MB   weight hi (fp16)
__device__ __half g_wlo[(size_t)N * K];    // 8 MB   weight lo (fp16 residual)

// ---------------- helpers ----------------
__device__ __forceinline__ uint32_t smem_u32(const void* p) {
    uint32_t a;
    asm("{ .reg .u64 t; cvta.to.shared.u64 t, %1; cvt.u32.u64 %0, t; }" : "=r"(a) : "l"(p));
    return a;
}
__device__ __forceinline__ void cp16(uint32_t dst, const void* src) {
    asm volatile("cp.async.cg.shared.global [%0], [%1], 16;\n" :: "r"(dst), "l"(src));
}
__device__ __forceinline__ void ldm_x4(uint32_t* r, uint32_t addr) {
    asm volatile("ldmatrix.sync.aligned.m8n8.x4.shared.b16 {%0,%1,%2,%3}, [%4];"
                 : "=r"(r[0]), "=r"(r[1]), "=r"(r[2]), "=r"(r[3]) : "r"(addr));
}
__device__ __forceinline__ void mma16816(float* d, const uint32_t* a, uint32_t b0, uint32_t b1) {
    asm volatile(
        "mma.sync.aligned.m16n8k16.row.col.f32.f16.f16.f32 "
        "{%0,%1,%2,%3}, {%4,%5,%6,%7}, {%8,%9}, {%0,%1,%2,%3};"
        : "+f"(d[0]), "+f"(d[1]), "+f"(d[2]), "+f"(d[3])
        : "r"(a[0]), "r"(a[1]), "r"(a[2]), "r"(a[3]), "r"(b0), "r"(b1));
}
__device__ __forceinline__ uint32_t sw128(uint32_t off) {
    return off ^ ((off >> 3) & 0x70);
}

// ---------------- prep kernels ----------------
__global__ void split_w_kernel(const float* __restrict__ w) {
    int i = blockIdx.x * blockDim.x + threadIdx.x;
    if (i < N * K) {
        float v = w[i];
        __half hi = __float2half_rn(v);
        float r = v - __half2float(hi);
        g_whi[i] = hi;
        g_wlo[i] = __float2half_rn(r);
    }
}

__global__ void conv_x_kernel(const float* __restrict__ x) {
    size_t i = (size_t)blockIdx.x * blockDim.x + threadIdx.x;
    if (i < ((size_t)M * K) / 4) {
        float4 v = __ldcs(&reinterpret_cast<const float4*>(x)[i]);
        __half2 h0 = __floats2half2_rn(v.x, v.y);
        __half2 h1 = __floats2half2_rn(v.z, v.w);
        uint2 packed;
        packed.x = *reinterpret_cast<uint32_t*>(&h0);
        packed.y = *reinterpret_cast<uint32_t*>(&h1);
        __stcs(&reinterpret_cast<uint2*>(g_xh)[i], packed);
    }
}

// ---------------- fused GEMM + LIF scan (resident-A, streamed-B inner loop) ----------------
__global__ void __launch_bounds__(256, 2) gemm_scan_kernel(float* __restrict__ out) {
    extern __shared__ char smem[];
    const uint32_t sb = smem_u32(smem);
    const int tid = threadIdx.x;
    const int lid = tid & 31;
    const int wid = tid >> 5;

    const int n0 = blockIdx.x * BN;
    const int b0 = blockIdx.y * BGRP;

    // warp layout: 2 (m: 80 rows) x 4 (n: 32 cols)
    const int wm = (wid & 1) * 80;
    const int wn = (wid >> 1) * 32;

    const int a_row = wm + (lid & 15);
    const int a_kb  = (lid >> 4) << 4;
    const int b_row = wn + (lid & 7) + ((lid >> 4) << 3);
    const int b_kb  = ((lid >> 3) & 1) << 4;

    auto issue = [&](int c) {
        if (c < NCHUNK) {
            const int k0 = c * BK;
            const uint32_t base = sb + (c & 1) * STAGE_B;
            // A: 160 rows (t-major: row = t*8 + b_l) x 8 chunks = 1280 cp16; 5/thread
            #pragma unroll
            for (int i = 0; i < 5; i++) {
                int id = tid + i * 256;
                int row = id >> 3, kc = id & 7;
                int t = row >> 3, b_l = row & 7;
                uint32_t soff = sw128((uint32_t)(row * 128 + kc * 16));
                cp16(base + soff,
                     g_xh + (size_t)(t * B + b0 + b_l) * K + k0 + kc * 8);
            }
            // W hi+lo: 128 rows x 8 chunks each = 2048 cp16; 8/thread
            #pragma unroll
            for (int i = 0; i < 4; i++) {
                int id = tid + i * 256;
                int row = id >> 3, kc = id & 7;
                uint32_t soff = sw128((uint32_t)(row * 128 + kc * 16));
                const size_t gco = (size_t)(n0 + row) * K + k0 + kc * 8;
                cp16(base + A_TILE_B + soff,              g_whi + gco);
                cp16(base + A_TILE_B + W_TILE_B + soff,   g_wlo + gco);
            }
        }
        asm volatile("cp.async.commit_group;\n" ::: "memory");
    };

    issue(0);

    float acc[5][4][4];
    #pragma unroll
    for (int i = 0; i < 5; i++)
        #pragma unroll
        for (int j = 0; j < 4; j++)
            #pragma unroll
            for (int r = 0; r < 4; r++) acc[i][j][r] = 0.0f;

    #pragma unroll 1
    for (int c = 0; c < NCHUNK; c++) {
        asm volatile("cp.async.wait_group 0;\n" ::: "memory");
        __syncthreads();
        issue(c + 1);

        const uint32_t sA  = sb + (c & 1) * STAGE_B;
        const uint32_t sBh = sA + A_TILE_B;
        const uint32_t sBl = sA + A_TILE_B + W_TILE_B;

        #pragma unroll
        for (int ks = 0; ks < 4; ks++) {
            // A resident (20 regs, all LDSMs issued up front for MLP), B streamed per bi
            uint32_t a[5][4];
            #pragma unroll
            for (int mi = 0; mi < 5; mi++) {
                uint32_t off = sw128((uint32_t)((a_row + mi * 16) * 128 + ks * 32 + a_kb));
                ldm_x4(a[mi], sA + off);
            }
            #pragma unroll
            for (int bi = 0; bi < 2; bi++) {
                uint32_t off = sw128((uint32_t)((b_row + bi * 16) * 128 + ks * 32 + b_kb));
                uint32_t bh[4], bl[4];
                ldm_x4(bh, sBh + off);
                ldm_x4(bl, sBl + off);
                #pragma unroll
                for (int mi = 0; mi < 5; mi++) {
                    #pragma unroll
                    for (int njj = 0; njj < 2; njj++) {
                        const int nj = bi * 2 + njj, pr = njj * 2;
                        mma16816(acc[mi][nj], a[mi], bh[pr], bh[pr + 1]);
                        mma16816(acc[mi][nj], a[mi], bl[pr], bl[pr + 1]);
                    }
                }
            }
        }
        __syncthreads();
    }
    asm volatile("cp.async.wait_group 0;\n" ::: "memory");
    __syncthreads();   // all warps done with smem tiles; reuse for scan staging

    // ---- epilogue 1: accumulators -> smem [row][o], row = t*8 + b_l ----
    float* sf = reinterpret_cast<float*>(smem);
    const int r_loc = wm + (lid >> 2);
    const int c_loc = wn + (lid & 3) * 2;
    #pragma unroll
    for (int mi = 0; mi < 5; mi++) {
        #pragma unroll
        for (int nj = 0; nj < 4; nj++) {
            sf[(r_loc + mi * 16)     * SSTRIDE + c_loc + nj * 8]     = acc[mi][nj][0];
            sf[(r_loc + mi * 16)     * SSTRIDE + c_loc + nj * 8 + 1] = acc[mi][nj][1];
            sf[(r_loc + mi * 16 + 8) * SSTRIDE + c_loc + nj * 8]     = acc[mi][nj][2];
            sf[(r_loc + mi * 16 + 8) * SSTRIDE + c_loc + nj * 8 + 1] = acc[mi][nj][3];
        }
    }
    __syncthreads();

    // ---- epilogue 2: LIF scan over t, write spikes directly ----
    const float alpha_s = 0.8f;
    const float alpha_m = 0.95f;
    const float inv_tau = 0.05f;
    #pragma unroll
    for (int i = 0; i < 4; i++) {
        const int p = tid + i * 256;          // 0..1023 = (b_l, o)
        const int b_l = p >> 7;
        const int o   = p & 127;
        float V = 0.0f, I = 0.0f;
        #pragma unroll
        for (int t = 0; t < T; t++) {
            float cu = sf[(t * 8 + b_l) * SSTRIDE + o];
            I = alpha_s * I + cu;
            V = alpha_m * V + inv_tau * I;
            float s = (V >= 1.0f) ? 1.0f : 0.0f;
            out[(size_t)(t * B + b0 + b_l) * N + n0 + o] = s;
            V = (V >= 1.0f) ? 0.0f : V;
        }
    }
}

// ---------------- launch ----------------
extern "C" void kernel_launch(void* const* d_in, const int* in_sizes, int n_in,
                              void* d_out, int out_size) {
    const float* x = (const float*)d_in[0];       // [T, B, IN] fp32, binary
    const float* w = (const float*)d_in[1];       // [OUT, IN]  fp32
    float* out = (float*)d_out;                   // [T, B, OUT] fp32

    cudaFuncSetAttribute(gemm_scan_kernel, cudaFuncAttributeMaxDynamicSharedMemorySize, SMEM_B);

    conv_x_kernel<<<(int)(((size_t)M * K / 4 + 255) / 256), 256>>>(x);
    split_w_kernel<<<(N * K + 255) / 256, 256>>>(w);
    gemm_scan_kernel<<<dim3(N / BN, B / BGRP), 256, SMEM_B>>>(out);
}

// round 17
// speedup vs baseline: 1.0501x; 1.0501x over previous
#include <cuda_runtime.h>
#include <cuda_fp16.h>
#include <cstdint>

// ---------------- Problem dims ----------------
static constexpr int T   = 20;
static constexpr int B   = 1024;
static constexpr int IN  = 2048;
static constexpr int OUT = 2048;
static constexpr int M   = T * B;          // 20480
static constexpr int K   = IN;             // 2048
static constexpr int N   = OUT;            // 2048

// GEMM tiling: 128x128x64, 256 threads, 2 CTAs/SM, 2 stages, SW128 swizzle (no pad)
static constexpr int BM = 128;
static constexpr int BN = 128;
static constexpr int BK = 64;              // 64 halfs = 128B row
static constexpr int NCHUNK = K / BK;      // 32

static constexpr int TILE_B  = 128 * 128;          // 16384 B per matrix tile
static constexpr int STAGE_B = 3 * TILE_B;         // A + Bhi + Blo = 49152
static constexpr int SMEM_B  = 2 * STAGE_B;        // 98304 (2 CTAs/SM -> 192KB)

// ---------------- scratch (no cudaMalloc allowed) ----------------
__device__ __half g_xh [(size_t)M * K];    // 84 MB  x in fp16 (exact: x is 0/1)
__device__ __half g_whi[(size_t)N * K];    // 8 MB   weight hi (fp16)
__device__ __half g_wlo[(size_t)N * K];    // 8 MB   weight lo (fp16 residual)
__device__ float  g_cur[(size_t)M * N];    // 168 MB GEMM result (fp32)

// ---------------- helpers ----------------
__device__ __forceinline__ uint32_t smem_u32(const void* p) {
    uint32_t a;
    asm("{ .reg .u64 t; cvta.to.shared.u64 t, %1; cvt.u32.u64 %0, t; }" : "=r"(a) : "l"(p));
    return a;
}
__device__ __forceinline__ void cp16(uint32_t dst, const void* src) {
    asm volatile("cp.async.cg.shared.global [%0], [%1], 16;\n" :: "r"(dst), "l"(src));
}
__device__ __forceinline__ void ldm_x4(uint32_t* r, uint32_t addr) {
    asm volatile("ldmatrix.sync.aligned.m8n8.x4.shared.b16 {%0,%1,%2,%3}, [%4];"
                 : "=r"(r[0]), "=r"(r[1]), "=r"(r[2]), "=r"(r[3]) : "r"(addr));
}
__device__ __forceinline__ void mma16816(float* d, const uint32_t* a, uint32_t b0, uint32_t b1) {
    asm volatile(
        "mma.sync.aligned.m16n8k16.row.col.f32.f16.f16.f32 "
        "{%0,%1,%2,%3}, {%4,%5,%6,%7}, {%8,%9}, {%0,%1,%2,%3};"
        : "+f"(d[0]), "+f"(d[1]), "+f"(d[2]), "+f"(d[3])
        : "r"(a[0]), "r"(a[1]), "r"(a[2]), "r"(a[3]), "r"(b0), "r"(b1));
}
__device__ __forceinline__ uint32_t sw128(uint32_t off) {
    return off ^ ((off >> 3) & 0x70);
}
// streaming (evict-first) 8B store — GEMM epilogue only
__device__ __forceinline__ void stg_cs_f2(float* p, float2 v) {
    asm volatile("st.global.cs.v2.f32 [%0], {%1, %2};" :: "l"(p), "f"(v.x), "f"(v.y) : "memory");
}

// ---------------- prep kernels ----------------
__global__ void split_w_kernel(const float* __restrict__ w) {
    int i = blockIdx.x * blockDim.x + threadIdx.x;
    if (i < N * K) {
        float v = w[i];
        __half hi = __float2half_rn(v);
        float r = v - __half2float(hi);
        g_whi[i] = hi;
        g_wlo[i] = __float2half_rn(r);
    }
}

__global__ void conv_x_kernel(const float* __restrict__ x) {
    size_t i = (size_t)blockIdx.x * blockDim.x + threadIdx.x;
    if (i < ((size_t)M * K) / 4) {
        // single-use stream: evict-first on both sides
        float4 v = __ldcs(&reinterpret_cast<const float4*>(x)[i]);
        __half2 h0 = __floats2half2_rn(v.x, v.y);
        __half2 h1 = __floats2half2_rn(v.z, v.w);
        uint2 packed;
        packed.x = *reinterpret_cast<uint32_t*>(&h0);
        packed.y = *reinterpret_cast<uint32_t*>(&h1);
        __stcs(&reinterpret_cast<uint2*>(g_xh)[i], packed);
    }
}

// ---------------- GEMM: 128x128x64, 256 thr, 2 CTAs/SM, fp16 2-split mma.sync ----------------
__global__ void __launch_bounds__(256, 2) gemm_kernel() {
    extern __shared__ char smem[];
    const uint32_t sb = smem_u32(smem);
    const int tid = threadIdx.x;
    const int lid = tid & 31;
    const int wid = tid >> 5;

    const int m0 = blockIdx.y * BM;
    const int n0 = blockIdx.x * BN;

    // warp layout: 2 (m) x 4 (n), warp tile 64x32
    const int wm = (wid & 1) * 64;
    const int wn = (wid >> 1) * 32;

    const int a_row = wm + (lid & 15);
    const int a_kb  = (lid >> 4) << 4;
    const int b_row = wn + (lid & 7) + ((lid >> 4) << 3);
    const int b_kb  = ((lid >> 3) & 1) << 4;

    auto issue = [&](int c) {
        if (c < NCHUNK) {
            const int k0 = c * BK;
            const uint32_t base = sb + (c & 1) * STAGE_B;
            #pragma unroll
            for (int i = 0; i < 4; i++) {
                int id = tid + i * 256;
                int row = id >> 3, kc = id & 7;
                uint32_t soff = sw128((uint32_t)(row * 128 + kc * 16));
                const size_t gco = k0 + kc * 8;
                cp16(base + soff,              g_xh  + (size_t)(m0 + row) * K + gco);
                cp16(base + TILE_B + soff,     g_whi + (size_t)(n0 + row) * K + gco);
                cp16(base + 2 * TILE_B + soff, g_wlo + (size_t)(n0 + row) * K + gco);
            }
        }
        asm volatile("cp.async.commit_group;\n" ::: "memory");
    };

    issue(0);

    float acc[4][4][4];
    #pragma unroll
    for (int i = 0; i < 4; i++)
        #pragma unroll
        for (int j = 0; j < 4; j++)
            #pragma unroll
            for (int r = 0; r < 4; r++) acc[i][j][r] = 0.0f;

    #pragma unroll 1
    for (int c = 0; c < NCHUNK; c++) {
        asm volatile("cp.async.wait_group 0;\n" ::: "memory");
        __syncthreads();
        issue(c + 1);

        const uint32_t sA  = sb + (c & 1) * STAGE_B;
        const uint32_t sBh = sA + TILE_B;
        const uint32_t sBl = sA + 2 * TILE_B;

        #pragma unroll
        for (int ks = 0; ks < 4; ks++) {
            uint32_t a[4][4];
            #pragma unroll
            for (int mi = 0; mi < 4; mi++) {
                uint32_t off = sw128((uint32_t)((a_row + mi * 16) * 128 + ks * 32 + a_kb));
                ldm_x4(a[mi], sA + off);
            }
            #pragma unroll
            for (int bi = 0; bi < 2; bi++) {
                uint32_t off = sw128((uint32_t)((b_row + bi * 16) * 128 + ks * 32 + b_kb));
                uint32_t bh[4], bl[4];
                ldm_x4(bh, sBh + off);
                ldm_x4(bl, sBl + off);
                #pragma unroll
                for (int mi = 0; mi < 4; mi++) {
                    #pragma unroll
                    for (int njj = 0; njj < 2; njj++) {
                        const int nj = bi * 2 + njj, pr = njj * 2;
                        mma16816(acc[mi][nj], a[mi], bh[pr], bh[pr + 1]);
                        mma16816(acc[mi][nj], a[mi], bl[pr], bl[pr + 1]);
                    }
                }
            }
        }
        __syncthreads();
    }

    // epilogue: streaming stores (keep W/A hot in L2)
    const int r_base = m0 + wm + (lid >> 2);
    const int c_base = n0 + wn + (lid & 3) * 2;
    #pragma unroll
    for (int mi = 0; mi < 4; mi++) {
        #pragma unroll
        for (int nj = 0; nj < 4; nj++) {
            stg_cs_f2(&g_cur[(size_t)(r_base + mi * 16) * N + c_base + nj * 8],
                      make_float2(acc[mi][nj][0], acc[mi][nj][1]));
            stg_cs_f2(&g_cur[(size_t)(r_base + mi * 16 + 8) * N + c_base + nj * 8],
                      make_float2(acc[mi][nj][2], acc[mi][nj][3]));
        }
    }
}

// ---------------- LIF scan kernel (plain loads/stores — roofline) ----------------
__global__ void scan_kernel(float* __restrict__ out) {
    const int id = blockIdx.x * blockDim.x + threadIdx.x;
    const int o = id & (N - 1);
    const int b = id >> 11;
    const float alpha_s = 0.8f;
    const float alpha_m = 0.95f;
    const float inv_tau = 0.05f;
    float V = 0.0f, I = 0.0f;
    #pragma unroll
    for (int t = 0; t < T; t++) {
        const size_t idx = ((size_t)(t * B + b)) * N + o;
        float cu = g_cur[idx];
        I = alpha_s * I + cu;
        V = alpha_m * V + inv_tau * I;
        float s = (V >= 1.0f) ? 1.0f : 0.0f;
        out[idx] = s;
        V = (V >= 1.0f) ? 0.0f : V;
    }
}

// ---------------- launch ----------------
extern "C" void kernel_launch(void* const* d_in, const int* in_sizes, int n_in,
                              void* d_out, int out_size) {
    const float* x = (const float*)d_in[0];       // [T, B, IN] fp32, binary
    const float* w = (const float*)d_in[1];       // [OUT, IN]  fp32
    float* out = (float*)d_out;                   // [T, B, OUT] fp32

    cudaFuncSetAttribute(gemm_kernel, cudaFuncAttributeMaxDynamicSharedMemorySize, SMEM_B);

    // conv_x first (streams 504MB with .cs), split_w last so W digits are L2-hot for GEMM
    conv_x_kernel<<<(int)(((size_t)M * K / 4 + 255) / 256), 256>>>(x);
    split_w_kernel<<<(N * K + 255) / 256, 256>>>(w);
    gemm_kernel<<<dim3(N / BN, M / BM), 256, SMEM_B>>>();
    scan_kernel<<<(B * N) / 256, 256>>>(out);
}